// round 4
// baseline (speedup 1.0000x reference)
#include <cuda_runtime.h>
#include <cuda_bf16.h>

#define NN   100000
#define EE   1600000
#define FIN  64
#define FOUT 32

// -------- scratch (static __device__, no allocations) --------
__device__ __align__(16) float g_deg[NN];          // degree -> d^{-1/2}
__device__ __align__(16) float g_agg[NN * FOUT];   // scatter target

// ---------------------------------------------------------------------------
// 1) zero deg + agg (float4 stores)
// ---------------------------------------------------------------------------
__global__ void zero_kernel() {
    int i = blockIdx.x * blockDim.x + threadIdx.x;
    if (i < NN * FOUT / 4)
        ((float4*)g_agg)[i] = make_float4(0.f, 0.f, 0.f, 0.f);
    if (i < NN) g_deg[i] = 0.f;
}

// ---------------------------------------------------------------------------
// 2) deg[row] += ew (scalar RED, spread)
// ---------------------------------------------------------------------------
__global__ void deg_kernel(const int* __restrict__ ei, const float* __restrict__ ew) {
    int e = blockIdx.x * blockDim.x + threadIdx.x;
    if (e < EE) atomicAdd(&g_deg[ei[e]], ew[e]);
}

// ---------------------------------------------------------------------------
// 3) dis = deg > 0 ? rsqrt(deg) : 0 (in place)
// ---------------------------------------------------------------------------
__global__ void dis_kernel() {
    int n = blockIdx.x * blockDim.x + threadIdx.x;
    if (n < NN) {
        float v = g_deg[n];
        g_deg[n] = (v > 0.0f) ? rsqrtf(v) : 0.0f;
    }
}

// ---------------------------------------------------------------------------
// 4) scatter SpMM with VECTOR reductions: 8 lanes per edge, each lane does
//    one float4 load of h[col] and ONE red.global.add.v4.f32 into agg[row].
//    51.2M scalar RED lanes (R0) -> 12.8M vector RED ops.
// ---------------------------------------------------------------------------
__device__ __forceinline__ void red4(float* p, float4 v) {
    asm volatile("red.global.add.v4.f32 [%0], {%1, %2, %3, %4};"
                 :: "l"(p), "f"(v.x), "f"(v.y), "f"(v.z), "f"(v.w)
                 : "memory");
}

__global__ void __launch_bounds__(256) spmm4_kernel(const int* __restrict__ ei,
                                                    const float* __restrict__ ew,
                                                    const float* __restrict__ h) {
    int t = blockIdx.x * 256 + threadIdx.x;     // EE*8 = 12.8M < 2^31
    int e = t >> 3;
    if (e >= EE) return;
    int sub = t & 7;
    int r = __ldg(ei + e);                       // 4 distinct addrs / warp, L1 hits
    int c = __ldg(ei + EE + e);
    float w = g_deg[r] * __ldg(ew + e) * g_deg[c];
    const float4 hv = *(const float4*)(h + (size_t)c * FOUT + sub * 4);  // coalesced 128B row
    red4(g_agg + (size_t)r * FOUT + sub * 4,
         make_float4(w * hv.x, w * hv.y, w * hv.z, w * hv.w));
}

// ---------------------------------------------------------------------------
// 5) fused dense: packed f32x2 FMA along K (unchanged from R1)
// ---------------------------------------------------------------------------
__device__ __forceinline__ unsigned long long pk(float lo, float hi) {
    unsigned long long r;
    asm("mov.b64 %0, {%1, %2};" : "=l"(r) : "f"(lo), "f"(hi));
    return r;
}
__device__ __forceinline__ void fma2(unsigned long long& d,
                                     unsigned long long a, unsigned long long b) {
    asm("fma.rn.f32x2 %0, %1, %2, %0;" : "+l"(d) : "l"(a), "l"(b));
}
__device__ __forceinline__ float hsum2(unsigned long long v) {
    float lo, hi;
    asm("mov.b64 {%0, %1}, %2;" : "=f"(lo), "=f"(hi) : "l"(v));
    return lo + hi;
}
__device__ __forceinline__ float sigf(float v) {
    return __fdividef(1.0f, 1.0f + __expf(-v));
}
__device__ __forceinline__ float tanh_(float v) {
    return fmaf(2.0f, sigf(2.0f * v), -1.0f);
}

#define UU 8   // nodes per warp-iteration
#define FUSED_SMEM (1024*16*2 + 512*16*4 + 32*16 + 32*4)

__global__ void __launch_bounds__(256) fused_kernel(
    const float* __restrict__ x,  const float* __restrict__ h,
    const float* __restrict__ c,
    const float* __restrict__ Wi, const float* __restrict__ bi,
    const float* __restrict__ thi, const float* __restrict__ cbi,
    const float* __restrict__ Wf, const float* __restrict__ bf,
    const float* __restrict__ thf, const float* __restrict__ cbf,
    const float* __restrict__ Wc, const float* __restrict__ bc,
    const float* __restrict__ thc, const float* __restrict__ cbc,
    const float* __restrict__ Wo, const float* __restrict__ bo,
    const float* __restrict__ tho, const float* __restrict__ cbo,
    const float* __restrict__ Wlin, const float* __restrict__ blin,
    float* __restrict__ out)
{
    extern __shared__ char smraw[];
    ulonglong2* sWIF  = (ulonglong2*)smraw;      // [kp(32)][lane(32)] (wI,wF) k-pairs
    ulonglong2* sWCO  = sWIF  + 1024;
    ulonglong2* sTIF0 = sWCO  + 1024;            // [jp(16)][lane] (tI0,tF0)
    ulonglong2* sTCO0 = sTIF0 + 512;
    ulonglong2* sTIF1 = sTCO0 + 512;             // pre-negated theta1
    ulonglong2* sTCO1 = sTIF1 + 512;
    float4*     sB    = (float4*)(sTCO1 + 512);  // combined bias per lane
    float*      sWl   = (float*)(sB + 32);

    int tid  = threadIdx.x;
    int lane = tid & 31;

    for (int i = tid; i < 1024; i += 256) {      // kp = i>>5, ln = i&31
        int kp = i >> 5, ln = i & 31;
        int i0 = kp * 64 + ln, i1 = kp * 64 + 32 + ln;
        sWIF[i] = make_ulonglong2(pk(Wi[i0], Wi[i1]), pk(Wf[i0], Wf[i1]));
        sWCO[i] = make_ulonglong2(pk(Wc[i0], Wc[i1]), pk(Wo[i0], Wo[i1]));
    }
    for (int i = tid; i < 512; i += 256) {       // jp = i>>5
        int jp = i >> 5, ln = i & 31;
        int i0 = jp * 64 + ln, i1 = jp * 64 + 32 + ln;
        sTIF0[i] = make_ulonglong2(pk(thi[i0], thi[i1]), pk(thf[i0], thf[i1]));
        sTCO0[i] = make_ulonglong2(pk(thc[i0], thc[i1]), pk(tho[i0], tho[i1]));
        sTIF1[i] = make_ulonglong2(pk(-thi[1024 + i0], -thi[1024 + i1]),
                                   pk(-thf[1024 + i0], -thf[1024 + i1]));
        sTCO1[i] = make_ulonglong2(pk(-thc[1024 + i0], -thc[1024 + i1]),
                                   pk(-tho[1024 + i0], -tho[1024 + i1]));
    }
    if (tid < FOUT) {
        sB[tid] = make_float4(bi[tid] + cbi[tid], bf[tid] + cbf[tid],
                              bc[tid] + cbc[tid], bo[tid] + cbo[tid]);
        sWl[tid] = Wlin[tid];
    }
    __syncthreads();

    const float  blin0 = __ldg(blin);
    const float4 bias  = sB[lane];
    int warp   = blockIdx.x * 8 + (tid >> 5);
    int nwarps = gridDim.x * 8;

    for (int base = warp * UU; base < NN; base += nwarps * UU) {
        unsigned long long accI[UU], accF[UU], accC[UU], accO[UU];
        #pragma unroll
        for (int u = 0; u < UU; u++) { accI[u]=0ull; accF[u]=0ull; accC[u]=0ull; accO[u]=0ull; }

        const ulonglong2* xp2 = (const ulonglong2*)(x + (size_t)base * FIN);   // 16 per row
        const ulonglong2* hp2 = (const ulonglong2*)(h + (size_t)base * FOUT);  // 8 per row
        const ulonglong2* ap2 = (const ulonglong2*)(g_agg + (size_t)base * FOUT);

        // x @ W : K = 64 (32 k-pairs, processed 2 per step)
        #pragma unroll 4
        for (int kk = 0; kk < 16; kk++) {
            ulonglong2 wIF0 = sWIF[(2*kk)   * 32 + lane];
            ulonglong2 wCO0 = sWCO[(2*kk)   * 32 + lane];
            ulonglong2 wIF1 = sWIF[(2*kk+1) * 32 + lane];
            ulonglong2 wCO1 = sWCO[(2*kk+1) * 32 + lane];
            #pragma unroll
            for (int u = 0; u < UU; u++) {
                ulonglong2 xv = xp2[u * 16 + kk];
                fma2(accI[u], xv.x, wIF0.x); fma2(accF[u], xv.x, wIF0.y);
                fma2(accC[u], xv.x, wCO0.x); fma2(accO[u], xv.x, wCO0.y);
                fma2(accI[u], xv.y, wIF1.x); fma2(accF[u], xv.y, wIF1.y);
                fma2(accC[u], xv.y, wCO1.x); fma2(accO[u], xv.y, wCO1.y);
            }
        }
        // + h @ theta0 - agg @ theta1 : K = 32 (16 j-pairs, 2 per step)
        #pragma unroll 2
        for (int jj = 0; jj < 8; jj++) {
            ulonglong2 tIF0a = sTIF0[(2*jj)   * 32 + lane];
            ulonglong2 tCO0a = sTCO0[(2*jj)   * 32 + lane];
            ulonglong2 tIF1a = sTIF1[(2*jj)   * 32 + lane];
            ulonglong2 tCO1a = sTCO1[(2*jj)   * 32 + lane];
            ulonglong2 tIF0b = sTIF0[(2*jj+1) * 32 + lane];
            ulonglong2 tCO0b = sTCO0[(2*jj+1) * 32 + lane];
            ulonglong2 tIF1b = sTIF1[(2*jj+1) * 32 + lane];
            ulonglong2 tCO1b = sTCO1[(2*jj+1) * 32 + lane];
            #pragma unroll
            for (int u = 0; u < UU; u++) {
                ulonglong2 hv = hp2[u * 8 + jj];
                ulonglong2 av = ap2[u * 8 + jj];
                fma2(accI[u], hv.x, tIF0a.x); fma2(accF[u], hv.x, tIF0a.y);
                fma2(accC[u], hv.x, tCO0a.x); fma2(accO[u], hv.x, tCO0a.y);
                fma2(accI[u], hv.y, tIF0b.x); fma2(accF[u], hv.y, tIF0b.y);
                fma2(accC[u], hv.y, tCO0b.x); fma2(accO[u], hv.y, tCO0b.y);
                fma2(accI[u], av.x, tIF1a.x); fma2(accF[u], av.x, tIF1a.y);
                fma2(accC[u], av.x, tCO1a.x); fma2(accO[u], av.x, tCO1a.y);
                fma2(accI[u], av.y, tIF1b.x); fma2(accF[u], av.y, tIF1b.y);
                fma2(accC[u], av.y, tCO1b.x); fma2(accO[u], av.y, tCO1b.y);
            }
        }
        // epilogue
        #pragma unroll
        for (int u = 0; u < UU; u++) {
            int n = base + u;
            if (n >= NN) break;
            float vI = sigf (hsum2(accI[u]) + bias.x);
            float vF = sigf (hsum2(accF[u]) + bias.y);
            float vT = tanh_(hsum2(accC[u]) + bias.z);
            float vO = sigf (hsum2(accO[u]) + bias.w);
            float cv = __ldg(c + (size_t)n * FOUT + lane);
            float Cn = fmaf(vF, cv, vI * vT);
            float Hn = vO * tanh_(Cn);
            float val = fmaxf(Hn, 0.0f) * sWl[lane];
            #pragma unroll
            for (int o = 16; o > 0; o >>= 1)
                val += __shfl_xor_sync(0xffffffffu, val, o);
            if (lane == 0) out[n] = val + blin0;
        }
    }
}

// ---------------------------------------------------------------------------
extern "C" void kernel_launch(void* const* d_in, const int* in_sizes, int n_in,
                              void* d_out, int out_size)
{
    const float* x    = (const float*)d_in[0];
    const int*   ei   = (const int*)  d_in[1];
    const float* ew   = (const float*)d_in[2];
    const float* h    = (const float*)d_in[3];
    const float* c    = (const float*)d_in[4];
    const float* Wi   = (const float*)d_in[5];
    const float* bi   = (const float*)d_in[6];
    const float* thi  = (const float*)d_in[7];
    const float* cbi  = (const float*)d_in[8];
    const float* Wf   = (const float*)d_in[9];
    const float* bf   = (const float*)d_in[10];
    const float* thf  = (const float*)d_in[11];
    const float* cbf  = (const float*)d_in[12];
    const float* Wc   = (const float*)d_in[13];
    const float* bc   = (const float*)d_in[14];
    const float* thc  = (const float*)d_in[15];
    const float* cbc  = (const float*)d_in[16];
    const float* Wo   = (const float*)d_in[17];
    const float* bo   = (const float*)d_in[18];
    const float* tho  = (const float*)d_in[19];
    const float* cbo  = (const float*)d_in[20];
    const float* Wlin = (const float*)d_in[21];
    const float* blin = (const float*)d_in[22];
    float* out = (float*)d_out;

    cudaFuncSetAttribute(fused_kernel,
                         cudaFuncAttributeMaxDynamicSharedMemorySize, FUSED_SMEM);

    zero_kernel<<<(NN * FOUT / 4 + 255) / 256, 256>>>();
    deg_kernel<<<(EE + 255) / 256, 256>>>(ei, ew);
    dis_kernel<<<(NN + 255) / 256, 256>>>();
    spmm4_kernel<<<(EE * 8 + 255) / 256, 256>>>(ei, ew, h);
    fused_kernel<<<296, 256, FUSED_SMEM>>>(
        x, h, c,
        Wi, bi, thi, cbi,
        Wf, bf, thf, cbf,
        Wc, bc, thc, cbc,
        Wo, bo, tho, cbo,
        Wlin, blin, out);
}

// round 5
// speedup vs baseline: 1.5992x; 1.5992x over previous
#include <cuda_runtime.h>
#include <cuda_bf16.h>

#define NN   100000
#define EE   1600000
#define FIN  64
#define FOUT 32

// -------- scratch (static __device__, no allocations) --------
__device__ __align__(16) float g_deg[NN];          // degree -> d^{-1/2}
__device__ __align__(16) float g_agg[NN * FOUT];   // scatter target

// ---------------------------------------------------------------------------
// 1) zero deg + agg (float4 stores)
// ---------------------------------------------------------------------------
__global__ void zero_kernel() {
    int i = blockIdx.x * blockDim.x + threadIdx.x;
    if (i < NN * FOUT / 4)
        ((float4*)g_agg)[i] = make_float4(0.f, 0.f, 0.f, 0.f);
    if (i < NN) g_deg[i] = 0.f;
}

// ---------------------------------------------------------------------------
// 2) deg[row] += ew (scalar RED, spread)
// ---------------------------------------------------------------------------
__global__ void deg_kernel(const int* __restrict__ ei, const float* __restrict__ ew) {
    int e = blockIdx.x * blockDim.x + threadIdx.x;
    if (e < EE) atomicAdd(&g_deg[e < EE ? ei[e] : 0], ew[e]);
}

// ---------------------------------------------------------------------------
// 3) dis = deg > 0 ? rsqrt(deg) : 0 (in place)
// ---------------------------------------------------------------------------
__global__ void dis_kernel() {
    int n = blockIdx.x * blockDim.x + threadIdx.x;
    if (n < NN) {
        float v = g_deg[n];
        g_deg[n] = (v > 0.0f) ? rsqrtf(v) : 0.0f;
    }
}

// ---------------------------------------------------------------------------
// 4) scatter SpMM, vector RED + broadcast: 8 lanes/edge. Only the sub==0 lane
//    loads ei/ew/deg (5 loads instead of 40 per warp); r,c,w shfl-broadcast
//    to the 8-lane group. Each lane: one float4 h load + one red.v4.f32.
// ---------------------------------------------------------------------------
__device__ __forceinline__ void red4(float* p, float4 v) {
    asm volatile("red.global.add.v4.f32 [%0], {%1, %2, %3, %4};"
                 :: "l"(p), "f"(v.x), "f"(v.y), "f"(v.z), "f"(v.w)
                 : "memory");
}

__global__ void __launch_bounds__(256) spmm4_kernel(const int* __restrict__ ei,
                                                    const float* __restrict__ ew,
                                                    const float* __restrict__ h) {
    int t = blockIdx.x * 256 + threadIdx.x;     // EE*8 = 12.8M < 2^31
    int e = t >> 3;
    if (e >= EE) return;
    int sub  = t & 7;
    int lane = threadIdx.x & 31;
    int src  = lane & ~7;                        // sub==0 lane of this group
    int r = 0, c = 0; float w = 0.f;
    if (sub == 0) {
        r = __ldg(ei + e);
        c = __ldg(ei + EE + e);
        w = g_deg[r] * __ldg(ew + e) * g_deg[c];
    }
    r = __shfl_sync(0xffffffffu, r, src);
    c = __shfl_sync(0xffffffffu, c, src);
    w = __shfl_sync(0xffffffffu, w, src);
    const float4 hv = *(const float4*)(h + (size_t)c * FOUT + sub * 4);  // coalesced 128B row
    red4(g_agg + (size_t)r * FOUT + sub * 4,
         make_float4(w * hv.x, w * hv.y, w * hv.z, w * hv.w));
}

// ---------------------------------------------------------------------------
// 5) fused dense (R0 scalar-FFMA version, measured ~77us)
// ---------------------------------------------------------------------------
__device__ __forceinline__ float sigf(float v) {
    return __fdividef(1.0f, 1.0f + __expf(-v));
}
__device__ __forceinline__ float tanh_(float v) {
    return fmaf(2.0f, sigf(2.0f * v), -1.0f);
}

#define SMEM_W4   (FIN * FOUT)         // 2048 float4 (W for 4 gates)
#define SMEM_T4   (FOUT * FOUT)        // 1024 float4 (theta[k] for 4 gates)
#define SMEM_BYTES ((SMEM_W4 + 2 * SMEM_T4 + FOUT) * 16 + FOUT * 4)

__global__ void __launch_bounds__(256) fused_kernel(
    const float* __restrict__ x,  const float* __restrict__ h,
    const float* __restrict__ c,
    const float* __restrict__ Wi, const float* __restrict__ bi,
    const float* __restrict__ thi, const float* __restrict__ cbi,
    const float* __restrict__ Wf, const float* __restrict__ bf,
    const float* __restrict__ thf, const float* __restrict__ cbf,
    const float* __restrict__ Wc, const float* __restrict__ bc,
    const float* __restrict__ thc, const float* __restrict__ cbc,
    const float* __restrict__ Wo, const float* __restrict__ bo,
    const float* __restrict__ tho, const float* __restrict__ cbo,
    const float* __restrict__ Wlin, const float* __restrict__ blin,
    float* __restrict__ out)
{
    extern __shared__ float4 sm[];
    float4* sW  = sm;                       // [FIN][FOUT] gate-interleaved
    float4* sT0 = sW  + SMEM_W4;            // [FOUT][FOUT]
    float4* sT1 = sT0 + SMEM_T4;            // [FOUT][FOUT]
    float4* sB  = sT1 + SMEM_T4;            // [FOUT] combined bias (b_g + cb_g)
    float*  sWl = (float*)(sB + FOUT);      // [FOUT]

    int tid = threadIdx.x;
    for (int i = tid; i < SMEM_W4; i += 256)
        sW[i] = make_float4(Wi[i], Wf[i], Wc[i], Wo[i]);
    for (int i = tid; i < SMEM_T4; i += 256) {
        sT0[i] = make_float4(thi[i],        thf[i],        thc[i],        tho[i]);
        sT1[i] = make_float4(thi[1024 + i], thf[1024 + i], thc[1024 + i], tho[1024 + i]);
    }
    if (tid < FOUT) {
        sB[tid] = make_float4(bi[tid] + cbi[tid], bf[tid] + cbf[tid],
                              bc[tid] + cbc[tid], bo[tid] + cbo[tid]);
        sWl[tid] = Wlin[tid];
    }
    __syncthreads();

    const float blin0 = __ldg(blin);
    int warp   = blockIdx.x * 8 + (tid >> 5);
    int lane   = tid & 31;
    int nwarps = gridDim.x * 8;

    const float4 bias = sB[lane];

    for (int base = warp * 4; base < NN; base += nwarps * 4) {
        float aI[4], aF[4], aC[4], aO[4];
        #pragma unroll
        for (int u = 0; u < 4; u++) {
            aI[u] = bias.x; aF[u] = bias.y; aC[u] = bias.z; aO[u] = bias.w;
        }
        const float* xr = x + base * FIN;
        const float* hr = h + base * FOUT;
        const float* ar = g_agg + base * FOUT;

        // x @ W_g  (K = 64)
        #pragma unroll 8
        for (int k = 0; k < FIN; k++) {
            float4 w = sW[k * FOUT + lane];
            #pragma unroll
            for (int u = 0; u < 4; u++) {
                float xv = __ldg(xr + u * FIN + k);     // warp broadcast
                aI[u] = fmaf(xv, w.x, aI[u]);
                aF[u] = fmaf(xv, w.y, aF[u]);
                aC[u] = fmaf(xv, w.z, aC[u]);
                aO[u] = fmaf(xv, w.w, aO[u]);
            }
        }
        // + h @ theta0_g  - agg @ theta1_g   (K = 32 each)
        #pragma unroll 8
        for (int j = 0; j < FOUT; j++) {
            float4 t0 = sT0[j * FOUT + lane];
            float4 t1 = sT1[j * FOUT + lane];
            #pragma unroll
            for (int u = 0; u < 4; u++) {
                float hv = __ldg(hr + u * FOUT + j);
                float av = __ldg(ar + u * FOUT + j);
                aI[u] = fmaf(hv, t0.x, aI[u]); aI[u] = fmaf(-av, t1.x, aI[u]);
                aF[u] = fmaf(hv, t0.y, aF[u]); aF[u] = fmaf(-av, t1.y, aF[u]);
                aC[u] = fmaf(hv, t0.z, aC[u]); aC[u] = fmaf(-av, t1.z, aC[u]);
                aO[u] = fmaf(hv, t0.w, aO[u]); aO[u] = fmaf(-av, t1.w, aO[u]);
            }
        }
        // LSTM epilogue + relu + Linear(32 -> 1) as warp reduction
        #pragma unroll
        for (int u = 0; u < 4; u++) {
            int n = base + u;
            if (n >= NN) break;
            float vI = sigf(aI[u]);
            float vF = sigf(aF[u]);
            float vT = tanh_(aC[u]);
            float vO = sigf(aO[u]);
            float cv = __ldg(c + n * FOUT + lane);
            float Cn = fmaf(vF, cv, vI * vT);
            float Hn = vO * tanh_(Cn);
            float val = fmaxf(Hn, 0.0f) * sWl[lane];
            #pragma unroll
            for (int o = 16; o > 0; o >>= 1)
                val += __shfl_xor_sync(0xffffffffu, val, o);
            if (lane == 0) out[n] = val + blin0;
        }
    }
}

// ---------------------------------------------------------------------------
extern "C" void kernel_launch(void* const* d_in, const int* in_sizes, int n_in,
                              void* d_out, int out_size)
{
    const float* x    = (const float*)d_in[0];
    const int*   ei   = (const int*)  d_in[1];
    const float* ew   = (const float*)d_in[2];
    const float* h    = (const float*)d_in[3];
    const float* c    = (const float*)d_in[4];
    const float* Wi   = (const float*)d_in[5];
    const float* bi   = (const float*)d_in[6];
    const float* thi  = (const float*)d_in[7];
    const float* cbi  = (const float*)d_in[8];
    const float* Wf   = (const float*)d_in[9];
    const float* bf   = (const float*)d_in[10];
    const float* thf  = (const float*)d_in[11];
    const float* cbf  = (const float*)d_in[12];
    const float* Wc   = (const float*)d_in[13];
    const float* bc   = (const float*)d_in[14];
    const float* thc  = (const float*)d_in[15];
    const float* cbc  = (const float*)d_in[16];
    const float* Wo   = (const float*)d_in[17];
    const float* bo   = (const float*)d_in[18];
    const float* tho  = (const float*)d_in[19];
    const float* cbo  = (const float*)d_in[20];
    const float* Wlin = (const float*)d_in[21];
    const float* blin = (const float*)d_in[22];
    float* out = (float*)d_out;

    cudaFuncSetAttribute(fused_kernel,
                         cudaFuncAttributeMaxDynamicSharedMemorySize, SMEM_BYTES);

    zero_kernel<<<(NN * FOUT / 4 + 255) / 256, 256>>>();
    deg_kernel<<<(EE + 255) / 256, 256>>>(ei, ew);
    dis_kernel<<<(NN + 255) / 256, 256>>>();
    spmm4_kernel<<<(EE * 8 + 255) / 256, 256>>>(ei, ew, h);
    fused_kernel<<<444, 256, SMEM_BYTES>>>(
        x, h, c,
        Wi, bi, thi, cbi,
        Wf, bf, thf, cbf,
        Wc, bc, thc, cbc,
        Wo, bo, tho, cbo,
        Wlin, blin, out);
}

// round 8
// speedup vs baseline: 1.6309x; 1.0198x over previous
#include <cuda_runtime.h>
#include <cuda_bf16.h>
#include <cstdint>

#define NN   100000
#define EE   1600000
#define FIN  64
#define FOUT 32
#define NTILE 128
#define NCTAS ((NN + NTILE - 1) / NTILE)   // 782

// -------- scratch (static __device__, no allocations) --------
__device__ __align__(16) float    g_deg[NN];
__device__ __align__(16) float    g_agg[NN * FOUT];
__device__ __align__(16) uint32_t g_Bhi[128 * 64];   // Theta hi, bf16x2 k-pairs, [n][kp]
__device__ __align__(16) uint32_t g_Blo[128 * 64];   // Theta lo

// ===========================================================================
// helpers
// ===========================================================================
__device__ __forceinline__ uint32_t pack_bf2(__nv_bfloat16 a, __nv_bfloat16 b) {
    __nv_bfloat162 t; t.x = a; t.y = b;
    return *(uint32_t*)&t;
}
__device__ __forceinline__ void split2(float a0, float a1, uint32_t& hi, uint32_t& lo) {
    __nv_bfloat16 h0 = __float2bfloat16(a0);
    __nv_bfloat16 h1 = __float2bfloat16(a1);
    float l0 = a0 - __bfloat162float(h0);
    float l1 = a1 - __bfloat162float(h1);
    hi = pack_bf2(h0, h1);
    lo = pack_bf2(__float2bfloat16(l0), __float2bfloat16(l1));
}
__device__ __forceinline__ void hmma(float* d, const uint32_t* a, uint32_t b0, uint32_t b1) {
    asm volatile(
        "mma.sync.aligned.m16n8k16.row.col.f32.bf16.bf16.f32 "
        "{%0,%1,%2,%3}, {%4,%5,%6,%7}, {%8,%9}, {%0,%1,%2,%3};"
        : "+f"(d[0]), "+f"(d[1]), "+f"(d[2]), "+f"(d[3])
        : "r"(a[0]), "r"(a[1]), "r"(a[2]), "r"(a[3]), "r"(b0), "r"(b1));
}
__device__ __forceinline__ float sigf(float v) {
    return __fdividef(1.0f, 1.0f + __expf(-v));
}
__device__ __forceinline__ float tanh_(float v) {
    return fmaf(2.0f, sigf(2.0f * v), -1.0f);
}

// ===========================================================================
// 1) zero deg + agg
// ===========================================================================
__global__ void zero_kernel() {
    int i = blockIdx.x * blockDim.x + threadIdx.x;
    if (i < NN * FOUT / 4)
        ((float4*)g_agg)[i] = make_float4(0.f, 0.f, 0.f, 0.f);
    if (i < NN) g_deg[i] = 0.f;
}

// ===========================================================================
// 2) pack combined weights Theta[n=g*32+f][k] as hi/lo bf16x2 k-pairs
//    k<64: W_g[k][f]; 64..95: th0_g[k-64][f]; 96..127: -th1_g[k-96][f]
// ===========================================================================
__global__ void bprep_kernel(const float* __restrict__ Wi, const float* __restrict__ thi,
                             const float* __restrict__ Wf, const float* __restrict__ thf,
                             const float* __restrict__ Wc, const float* __restrict__ thc,
                             const float* __restrict__ Wo, const float* __restrict__ tho) {
    int i = blockIdx.x * 256 + threadIdx.x;
    if (i >= 128 * 64) return;
    int n = i >> 6, kp = i & 63;
    int g = n >> 5, f = n & 31;
    const float* W  = (g == 0) ? Wi  : (g == 1) ? Wf  : (g == 2) ? Wc  : Wo;
    const float* th = (g == 0) ? thi : (g == 1) ? thf : (g == 2) ? thc : tho;
    float v[2];
    #pragma unroll
    for (int q = 0; q < 2; q++) {
        int k = kp * 2 + q;
        if (k < 64)      v[q] = W[k * 32 + f];
        else if (k < 96) v[q] = th[(k - 64) * 32 + f];
        else             v[q] = -th[1024 + (k - 96) * 32 + f];
    }
    uint32_t hi, lo;
    split2(v[0], v[1], hi, lo);
    g_Bhi[i] = hi;
    g_Blo[i] = lo;
}

// ===========================================================================
// 3) deg[row] += ew ; 4) dis = rsqrt(deg)
// ===========================================================================
__global__ void deg_kernel(const int* __restrict__ ei, const float* __restrict__ ew) {
    int e = blockIdx.x * blockDim.x + threadIdx.x;
    if (e < EE) atomicAdd(&g_deg[ei[e]], ew[e]);
}
__global__ void dis_kernel() {
    int n = blockIdx.x * blockDim.x + threadIdx.x;
    if (n < NN) {
        float v = g_deg[n];
        g_deg[n] = (v > 0.0f) ? rsqrtf(v) : 0.0f;
    }
}

// ===========================================================================
// 5) scatter SpMM, vector RED + shfl broadcast (R5, measured 56us)
// ===========================================================================
__device__ __forceinline__ void red4(float* p, float4 v) {
    asm volatile("red.global.add.v4.f32 [%0], {%1, %2, %3, %4};"
                 :: "l"(p), "f"(v.x), "f"(v.y), "f"(v.z), "f"(v.w) : "memory");
}

__global__ void __launch_bounds__(256) spmm4_kernel(const int* __restrict__ ei,
                                                    const float* __restrict__ ew,
                                                    const float* __restrict__ h) {
    int t = blockIdx.x * 256 + threadIdx.x;
    int e = t >> 3;
    if (e >= EE) return;
    int sub  = t & 7;
    int lane = threadIdx.x & 31;
    int src  = lane & ~7;
    int r = 0, c = 0; float w = 0.f;
    if (sub == 0) {
        r = __ldg(ei + e);
        c = __ldg(ei + EE + e);
        w = g_deg[r] * __ldg(ew + e) * g_deg[c];
    }
    r = __shfl_sync(0xffffffffu, r, src);
    c = __shfl_sync(0xffffffffu, c, src);
    w = __shfl_sync(0xffffffffu, w, src);
    const float4 hv = *(const float4*)(h + (size_t)c * FOUT + sub * 4);
    red4(g_agg + (size_t)r * FOUT + sub * 4,
         make_float4(w * hv.x, w * hv.y, w * hv.z, w * hv.w));
}

// ===========================================================================
// 6) dense HMMA kernel: D[128 nodes][128 gates] = A(hi/lo) @ Theta^T(hi/lo)
//    + fused LSTM epilogue + relu + W_lin.
// ===========================================================================
#define ASTRIDE 65      // uint32 words per row (padded, conflict-free)
#define DSTRIDE 129     // float words per row (padded, conflict-free)

#define SM_AHI 0
#define SM_ALO (SM_AHI + 128 * ASTRIDE * 4)     //  33280
#define SM_BHI (SM_ALO + 128 * ASTRIDE * 4)     //  66560
#define SM_BLO (SM_BHI + 128 * ASTRIDE * 4)     //  99840
#define SM_BIAS (SM_BLO + 128 * ASTRIDE * 4)    // 133120
#define SM_WL   (SM_BIAS + 128 * 4)             // 133632
#define SM_TOTAL (SM_WL + 32 * 4 + 16)
// D (float[128][129] = 66048 B) overlays SM_AHI..SM_BHI (66560 B)

__global__ void __launch_bounds__(256, 1) dense_kernel(
    const float* __restrict__ x, const float* __restrict__ h,
    const float* __restrict__ c,
    const float* __restrict__ bi, const float* __restrict__ cbi,
    const float* __restrict__ bf_, const float* __restrict__ cbf,
    const float* __restrict__ bc, const float* __restrict__ cbc,
    const float* __restrict__ bo, const float* __restrict__ cbo,
    const float* __restrict__ Wlin, const float* __restrict__ blin,
    float* __restrict__ out)
{
    extern __shared__ char sm[];
    uint32_t* sAhi = (uint32_t*)(sm + SM_AHI);
    uint32_t* sAlo = (uint32_t*)(sm + SM_ALO);
    uint32_t* sBhi = (uint32_t*)(sm + SM_BHI);
    uint32_t* sBlo = (uint32_t*)(sm + SM_BLO);
    float*    sBias = (float*)(sm + SM_BIAS);
    float*    sWl   = (float*)(sm + SM_WL);
    float*    sD    = (float*)(sm + SM_AHI);    // overlay after MMA

    int tid  = threadIdx.x;
    int warp = tid >> 5;
    int lane = tid & 31;
    int gID  = lane >> 2;      // 0..7
    int tig  = lane & 3;       // 0..3

    // ---- load B (pre-packed) into padded smem ----
    for (int i = tid; i < 128 * 64; i += 256) {
        int n = i >> 6, kp = i & 63;
        sBhi[n * ASTRIDE + kp] = g_Bhi[i];
        sBlo[n * ASTRIDE + kp] = g_Blo[i];
    }
    // ---- bias + W_lin ----
    if (tid < 128) {
        int g = tid >> 5, f = tid & 31;
        const float* b  = (g == 0) ? bi  : (g == 1) ? bf_ : (g == 2) ? bc  : bo;
        const float* cb = (g == 0) ? cbi : (g == 1) ? cbf : (g == 2) ? cbc : cbo;
        sBias[tid] = b[f] + cb[f];
        if (tid < 32) sWl[tid] = Wlin[tid];
    }

    // ---- convert A rows (x|h|agg) to hi/lo bf16x2 ----
    {
        int nl   = tid >> 1;                  // local node 0..127
        int half = tid & 1;                   // 0: k 0..63, 1: k 64..127
        int node = blockIdx.x * NTILE + nl;
        uint32_t* dh = sAhi + nl * ASTRIDE + half * 32;
        uint32_t* dl = sAlo + nl * ASTRIDE + half * 32;
        if (node < NN) {
            if (half == 0) {
                const float4* xp = (const float4*)(x + (size_t)node * FIN);
                #pragma unroll
                for (int q = 0; q < 16; q++) {
                    float4 v = __ldg(xp + q);
                    split2(v.x, v.y, dh[q*2],   dl[q*2]);
                    split2(v.z, v.w, dh[q*2+1], dl[q*2+1]);
                }
            } else {
                const float4* hp = (const float4*)(h + (size_t)node * FOUT);
                const float4* ap = (const float4*)(g_agg + (size_t)node * FOUT);
                #pragma unroll
                for (int q = 0; q < 8; q++) {
                    float4 v = __ldg(hp + q);
                    split2(v.x, v.y, dh[q*2],   dl[q*2]);
                    split2(v.z, v.w, dh[q*2+1], dl[q*2+1]);
                }
                #pragma unroll
                for (int q = 0; q < 8; q++) {
                    float4 v = ap[q];
                    split2(v.x, v.y, dh[16 + q*2],   dl[16 + q*2]);
                    split2(v.z, v.w, dh[16 + q*2+1], dl[16 + q*2+1]);
                }
            }
        } else {
            #pragma unroll
            for (int q = 0; q < 32; q++) { dh[q] = 0u; dl[q] = 0u; }
        }
    }
    __syncthreads();

    // ---- MMA: warp owns 16 node-rows, all 128 output cols ----
    float acc[16][4];
    #pragma unroll
    for (int nt = 0; nt < 16; nt++)
        #pragma unroll
        for (int q = 0; q < 4; q++) acc[nt][q] = 0.f;

    int r0 = warp * 16 + gID;          // fragment row (node-local)
    int r1 = r0 + 8;

    #pragma unroll
    for (int ks = 0; ks < 8; ks++) {
        int kc = ks * 8 + tig;
        uint32_t ah[4], al[4];
        ah[0] = sAhi[r0 * ASTRIDE + kc];     al[0] = sAlo[r0 * ASTRIDE + kc];
        ah[1] = sAhi[r1 * ASTRIDE + kc];     al[1] = sAlo[r1 * ASTRIDE + kc];
        ah[2] = sAhi[r0 * ASTRIDE + kc + 4]; al[2] = sAlo[r0 * ASTRIDE + kc + 4];
        ah[3] = sAhi[r1 * ASTRIDE + kc + 4]; al[3] = sAlo[r1 * ASTRIDE + kc + 4];
        #pragma unroll
        for (int nt = 0; nt < 16; nt++) {
            int nrow = nt * 8 + gID;
            uint32_t bh0 = sBhi[nrow * ASTRIDE + kc];
            uint32_t bh1 = sBhi[nrow * ASTRIDE + kc + 4];
            uint32_t bl0 = sBlo[nrow * ASTRIDE + kc];
            uint32_t bl1 = sBlo[nrow * ASTRIDE + kc + 4];
            hmma(acc[nt], ah, bh0, bh1);
            hmma(acc[nt], al, bh0, bh1);
            hmma(acc[nt], ah, bl0, bl1);
        }
    }
    __syncthreads();   // A dead; safe to overlay D

    // ---- store D to smem ----
    #pragma unroll
    for (int nt = 0; nt < 16; nt++) {
        int col = nt * 8 + tig * 2;
        sD[r0 * DSTRIDE + col]     = acc[nt][0];
        sD[r0 * DSTRIDE + col + 1] = acc[nt][1];
        sD[r1 * DSTRIDE + col]     = acc[nt][2];
        sD[r1 * DSTRIDE + col + 1] = acc[nt][3];
    }
    __syncthreads();

    // ---- epilogue: 2 threads per node ----
    {
        int nl   = tid >> 1;
        int sel  = tid & 1;
        int node = blockIdx.x * NTILE + nl;
        const float* drow = sD + nl * DSTRIDE;
        float part = 0.f;
        if (node < NN) {
            const float* cp = c + (size_t)node * FOUT;
            #pragma unroll
            for (int q = 0; q < 16; q++) {
                int f = sel * 16 + q;
                float vI = sigf (drow[f]      + sBias[f]);
                float vF = sigf (drow[32 + f] + sBias[32 + f]);
                float vT = tanh_(drow[64 + f] + sBias[64 + f]);
                float vO = sigf (drow[96 + f] + sBias[96 + f]);
                float Cn = fmaf(vF, __ldg(cp + f), vI * vT);
                float Hn = vO * tanh_(Cn);
                part = fmaf(fmaxf(Hn, 0.f), sWl[f], part);
            }
        }
        float tot = part + __shfl_xor_sync(0xffffffffu, part, 1);
        if (sel == 0 && node < NN) out[node] = tot + __ldg(blin);
    }
}

// ===========================================================================
extern "C" void kernel_launch(void* const* d_in, const int* in_sizes, int n_in,
                              void* d_out, int out_size)
{
    const float* x    = (const float*)d_in[0];
    const int*   ei   = (const int*)  d_in[1];
    const float* ew   = (const float*)d_in[2];
    const float* h    = (const float*)d_in[3];
    const float* c    = (const float*)d_in[4];
    const float* Wi   = (const float*)d_in[5];
    const float* bi   = (const float*)d_in[6];
    const float* thi  = (const float*)d_in[7];
    const float* cbi  = (const float*)d_in[8];
    const float* Wf   = (const float*)d_in[9];
    const float* bf   = (const float*)d_in[10];
    const float* thf  = (const float*)d_in[11];
    const float* cbf  = (const float*)d_in[12];
    const float* Wc   = (const float*)d_in[13];
    const float* bc   = (const float*)d_in[14];
    const float* thc  = (const float*)d_in[15];
    const float* cbc  = (const float*)d_in[16];
    const float* Wo   = (const float*)d_in[17];
    const float* bo   = (const float*)d_in[18];
    const float* tho  = (const float*)d_in[19];
    const float* cbo  = (const float*)d_in[20];
    const float* Wlin = (const float*)d_in[21];
    const float* blin = (const float*)d_in[22];
    float* out = (float*)d_out;

    cudaFuncSetAttribute(dense_kernel,
                         cudaFuncAttributeMaxDynamicSharedMemorySize, SM_TOTAL);

    zero_kernel<<<(NN * FOUT / 4 + 255) / 256, 256>>>();
    bprep_kernel<<<32, 256>>>(Wi, thi, Wf, thf, Wc, thc, Wo, tho);
    deg_kernel<<<(EE + 255) / 256, 256>>>(ei, ew);
    dis_kernel<<<(NN + 255) / 256, 256>>>();
    spmm4_kernel<<<(EE * 8 + 255) / 256, 256>>>(ei, ew, h);
    dense_kernel<<<NCTAS, 256, SM_TOTAL>>>(
        x, h, c,
        bi, cbi, bf, cbf, bc, cbc, bo, cbo,
        Wlin, blin, out);
}

// round 10
// speedup vs baseline: 2.0632x; 1.2651x over previous
#include <cuda_runtime.h>
#include <cuda_bf16.h>
#include <cstdint>

#define NN   100000
#define EE   1600000
#define FIN  64
#define FOUT 32
#define NTILE 128
#define NCTAS ((NN + NTILE - 1) / NTILE)   // 782

// -------- scratch (static __device__, no allocations) --------
__device__ __align__(16) float    g_deg[NN];
__device__ __align__(16) float    g_agg[NN * FOUT];
__device__ __align__(16) uint32_t g_Bhi[128 * 64];   // Theta hi, bf16x2 k-pairs, [n][kp]
__device__ __align__(16) uint32_t g_Blo[128 * 64];   // Theta lo

// ===========================================================================
// helpers
// ===========================================================================
__device__ __forceinline__ uint32_t pack_bf2(__nv_bfloat16 a, __nv_bfloat16 b) {
    __nv_bfloat162 t; t.x = a; t.y = b;
    return *(uint32_t*)&t;
}
__device__ __forceinline__ void split2(float a0, float a1, uint32_t& hi, uint32_t& lo) {
    __nv_bfloat16 h0 = __float2bfloat16(a0);
    __nv_bfloat16 h1 = __float2bfloat16(a1);
    float l0 = a0 - __bfloat162float(h0);
    float l1 = a1 - __bfloat162float(h1);
    hi = pack_bf2(h0, h1);
    lo = pack_bf2(__float2bfloat16(l0), __float2bfloat16(l1));
}
__device__ __forceinline__ void hmma(float* d, const uint32_t* a, uint32_t b0, uint32_t b1) {
    asm volatile(
        "mma.sync.aligned.m16n8k16.row.col.f32.bf16.bf16.f32 "
        "{%0,%1,%2,%3}, {%4,%5,%6,%7}, {%8,%9}, {%0,%1,%2,%3};"
        : "+f"(d[0]), "+f"(d[1]), "+f"(d[2]), "+f"(d[3])
        : "r"(a[0]), "r"(a[1]), "r"(a[2]), "r"(a[3]), "r"(b0), "r"(b1));
}
__device__ __forceinline__ float sigf(float v) {
    return __fdividef(1.0f, 1.0f + __expf(-v));
}
__device__ __forceinline__ float tanh_(float v) {
    return fmaf(2.0f, sigf(2.0f * v), -1.0f);
}

// ===========================================================================
// 1) zero deg + agg, AND pack combined weights (independent work, one launch)
//    Theta[n=g*32+f][k]: k<64: W_g[k][f]; 64..95: th0_g[k-64][f];
//    96..127: -th1_g[k-96][f]  -> hi/lo bf16x2 k-pairs
// ===========================================================================
__global__ void prep_kernel(const float* __restrict__ Wi, const float* __restrict__ thi,
                            const float* __restrict__ Wf, const float* __restrict__ thf,
                            const float* __restrict__ Wc, const float* __restrict__ thc,
                            const float* __restrict__ Wo, const float* __restrict__ tho) {
    int i = blockIdx.x * blockDim.x + threadIdx.x;
    if (i < NN * FOUT / 4)
        ((float4*)g_agg)[i] = make_float4(0.f, 0.f, 0.f, 0.f);
    if (i < NN) g_deg[i] = 0.f;
    if (i < 128 * 64) {
        int n = i >> 6, kp = i & 63;
        int g = n >> 5, f = n & 31;
        const float* W  = (g == 0) ? Wi  : (g == 1) ? Wf  : (g == 2) ? Wc  : Wo;
        const float* th = (g == 0) ? thi : (g == 1) ? thf : (g == 2) ? thc : tho;
        float v[2];
        #pragma unroll
        for (int q = 0; q < 2; q++) {
            int k = kp * 2 + q;
            if (k < 64)      v[q] = W[k * 32 + f];
            else if (k < 96) v[q] = th[(k - 64) * 32 + f];
            else             v[q] = -th[1024 + (k - 96) * 32 + f];
        }
        uint32_t hi, lo;
        split2(v[0], v[1], hi, lo);
        g_Bhi[i] = hi;
        g_Blo[i] = lo;
    }
}

// ===========================================================================
// 2) deg[row] += ew
// ===========================================================================
__global__ void deg_kernel(const int* __restrict__ ei, const float* __restrict__ ew) {
    int e = blockIdx.x * blockDim.x + threadIdx.x;
    if (e < EE) atomicAdd(&g_deg[ei[e]], ew[e]);
}

// ===========================================================================
// 3) scatter SpMM, vector RED + shfl broadcast; rsqrt computed inline
// ===========================================================================
__device__ __forceinline__ void red4(float* p, float4 v) {
    asm volatile("red.global.add.v4.f32 [%0], {%1, %2, %3, %4};"
                 :: "l"(p), "f"(v.x), "f"(v.y), "f"(v.z), "f"(v.w) : "memory");
}

__global__ void __launch_bounds__(256) spmm4_kernel(const int* __restrict__ ei,
                                                    const float* __restrict__ ew,
                                                    const float* __restrict__ h) {
    int t = blockIdx.x * 256 + threadIdx.x;
    int e = t >> 3;
    if (e >= EE) return;
    int sub  = t & 7;
    int lane = threadIdx.x & 31;
    int src  = lane & ~7;
    int r = 0, c = 0; float w = 0.f;
    if (sub == 0) {
        r = __ldg(ei + e);
        c = __ldg(ei + EE + e);
        float dr = g_deg[r], dc = g_deg[c];
        float ir = (dr > 0.f) ? rsqrtf(dr) : 0.f;
        float ic = (dc > 0.f) ? rsqrtf(dc) : 0.f;
        w = ir * __ldg(ew + e) * ic;
    }
    r = __shfl_sync(0xffffffffu, r, src);
    c = __shfl_sync(0xffffffffu, c, src);
    w = __shfl_sync(0xffffffffu, w, src);
    const float4 hv = *(const float4*)(h + (size_t)c * FOUT + sub * 4);
    red4(g_agg + (size_t)r * FOUT + sub * 4,
         make_float4(w * hv.x, w * hv.y, w * hv.z, w * hv.w));
}

// ===========================================================================
// 4) dense HMMA kernel: D[128 nodes][128 gates] = A(hi/lo) @ Theta^T(hi/lo)
//    + fused LSTM epilogue + relu + W_lin.
//    ASTRIDE=68 (68 mod 32 == 4): fragment access bank = gID*4+tig -> all 32
//    lanes distinct -> conflict-free MMA-phase LDS.
// ===========================================================================
#define ASTRIDE 68      // uint32 words per row
#define DSTRIDE 129     // float words per row (conflict-free epilogue reads)

#define SM_AHI 0
#define SM_ALO (SM_AHI + 128 * ASTRIDE * 4)     //  34816
#define SM_BHI (SM_ALO + 128 * ASTRIDE * 4)     //  69632
#define SM_BLO (SM_BHI + 128 * ASTRIDE * 4)     // 104448
#define SM_BIAS (SM_BLO + 128 * ASTRIDE * 4)    // 139264
#define SM_WL   (SM_BIAS + 128 * 4)             // 139776
#define SM_TOTAL (SM_WL + 32 * 4 + 16)
// D (float[128][129] = 66048 B) overlays SM_AHI..SM_BHI (69632 B)

__global__ void __launch_bounds__(256, 1) dense_kernel(
    const float* __restrict__ x, const float* __restrict__ h,
    const float* __restrict__ c,
    const float* __restrict__ bi, const float* __restrict__ cbi,
    const float* __restrict__ bf_, const float* __restrict__ cbf,
    const float* __restrict__ bc, const float* __restrict__ cbc,
    const float* __restrict__ bo, const float* __restrict__ cbo,
    const float* __restrict__ Wlin, const float* __restrict__ blin,
    float* __restrict__ out)
{
    extern __shared__ char sm[];
    uint32_t* sAhi = (uint32_t*)(sm + SM_AHI);
    uint32_t* sAlo = (uint32_t*)(sm + SM_ALO);
    uint32_t* sBhi = (uint32_t*)(sm + SM_BHI);
    uint32_t* sBlo = (uint32_t*)(sm + SM_BLO);
    float*    sBias = (float*)(sm + SM_BIAS);
    float*    sWl   = (float*)(sm + SM_WL);
    float*    sD    = (float*)(sm + SM_AHI);    // overlay after MMA

    int tid  = threadIdx.x;
    int warp = tid >> 5;
    int lane = tid & 31;
    int gID  = lane >> 2;      // 0..7
    int tig  = lane & 3;       // 0..3

    // ---- load B (pre-packed) into padded smem ----
    for (int i = tid; i < 128 * 64; i += 256) {
        int n = i >> 6, kp = i & 63;
        sBhi[n * ASTRIDE + kp] = g_Bhi[i];
        sBlo[n * ASTRIDE + kp] = g_Blo[i];
    }
    // ---- bias + W_lin ----
    if (tid < 128) {
        int g = tid >> 5, f = tid & 31;
        const float* b  = (g == 0) ? bi  : (g == 1) ? bf_ : (g == 2) ? bc  : bo;
        const float* cb = (g == 0) ? cbi : (g == 1) ? cbf : (g == 2) ? cbc : cbo;
        sBias[tid] = b[f] + cb[f];
        if (tid < 32) sWl[tid] = Wlin[tid];
    }

    // ---- convert A rows (x|h|agg) to hi/lo bf16x2 ----
    {
        int nl   = tid >> 1;                  // local node 0..127
        int half = tid & 1;                   // 0: k 0..63, 1: k 64..127
        int node = blockIdx.x * NTILE + nl;
        uint32_t* dh = sAhi + nl * ASTRIDE + half * 32;
        uint32_t* dl = sAlo + nl * ASTRIDE + half * 32;
        if (node < NN) {
            if (half == 0) {
                const float4* xp = (const float4*)(x + (size_t)node * FIN);
                #pragma unroll
                for (int q = 0; q < 16; q++) {
                    float4 v = __ldg(xp + q);
                    split2(v.x, v.y, dh[q*2],   dl[q*2]);
                    split2(v.z, v.w, dh[q*2+1], dl[q*2+1]);
                }
            } else {
                const float4* hp = (const float4*)(h + (size_t)node * FOUT);
                const float4* ap = (const float4*)(g_agg + (size_t)node * FOUT);
                #pragma unroll
                for (int q = 0; q < 8; q++) {
                    float4 v = __ldg(hp + q);
                    split2(v.x, v.y, dh[q*2],   dl[q*2]);
                    split2(v.z, v.w, dh[q*2+1], dl[q*2+1]);
                }
                #pragma unroll
                for (int q = 0; q < 8; q++) {
                    float4 v = ap[q];
                    split2(v.x, v.y, dh[16 + q*2],   dl[16 + q*2]);
                    split2(v.z, v.w, dh[16 + q*2+1], dl[16 + q*2+1]);
                }
            }
        } else {
            #pragma unroll
            for (int q = 0; q < 32; q++) { dh[q] = 0u; dl[q] = 0u; }
        }
    }
    __syncthreads();

    // ---- MMA: warp owns 16 node-rows, all 128 output cols ----
    float acc[16][4];
    #pragma unroll
    for (int nt = 0; nt < 16; nt++)
        #pragma unroll
        for (int q = 0; q < 4; q++) acc[nt][q] = 0.f;

    int r0 = warp * 16 + gID;          // fragment row (node-local)
    int r1 = r0 + 8;

    #pragma unroll
    for (int ks = 0; ks < 8; ks++) {
        int kc = ks * 8 + tig;
        uint32_t ah[4], al[4];
        ah[0] = sAhi[r0 * ASTRIDE + kc];     al[0] = sAlo[r0 * ASTRIDE + kc];
        ah[1] = sAhi[r1 * ASTRIDE + kc];     al[1] = sAlo[r1 * ASTRIDE + kc];
        ah[2] = sAhi[r0 * ASTRIDE + kc + 4]; al[2] = sAlo[r0 * ASTRIDE + kc + 4];
        ah[3] = sAhi[r1 * ASTRIDE + kc + 4]; al[3] = sAlo[r1 * ASTRIDE + kc + 4];
        #pragma unroll
        for (int nt = 0; nt < 16; nt++) {
            int nrow = nt * 8 + gID;
            uint32_t bh0 = sBhi[nrow * ASTRIDE + kc];
            uint32_t bh1 = sBhi[nrow * ASTRIDE + kc + 4];
            uint32_t bl0 = sBlo[nrow * ASTRIDE + kc];
            uint32_t bl1 = sBlo[nrow * ASTRIDE + kc + 4];
            hmma(acc[nt], ah, bh0, bh1);
            hmma(acc[nt], al, bh0, bh1);
            hmma(acc[nt], ah, bl0, bl1);
        }
    }
    __syncthreads();   // A dead; safe to overlay D

    // ---- store D to smem ----
    #pragma unroll
    for (int nt = 0; nt < 16; nt++) {
        int col = nt * 8 + tig * 2;
        sD[r0 * DSTRIDE + col]     = acc[nt][0];
        sD[r0 * DSTRIDE + col + 1] = acc[nt][1];
        sD[r1 * DSTRIDE + col]     = acc[nt][2];
        sD[r1 * DSTRIDE + col + 1] = acc[nt][3];
    }
    __syncthreads();

    // ---- epilogue: 2 threads per node ----
    {
        int nl   = tid >> 1;
        int sel  = tid & 1;
        int node = blockIdx.x * NTILE + nl;
        const float* drow = sD + nl * DSTRIDE;
        float part = 0.f;
        if (node < NN) {
            const float* cp = c + (size_t)node * FOUT;
            #pragma unroll
            for (int q = 0; q < 16; q++) {
                int f = sel * 16 + q;
                float vI = sigf (drow[f]      + sBias[f]);
                float vF = sigf (drow[32 + f] + sBias[32 + f]);
                float vT = tanh_(drow[64 + f] + sBias[64 + f]);
                float vO = sigf (drow[96 + f] + sBias[96 + f]);
                float Cn = fmaf(vF, __ldg(cp + f), vI * vT);
                float Hn = vO * tanh_(Cn);
                part = fmaf(fmaxf(Hn, 0.f), sWl[f], part);
            }
        }
        float tot = part + __shfl_xor_sync(0xffffffffu, part, 1);
        if (sel == 0 && node < NN) out[node] = tot + __ldg(blin);
    }
}

// ===========================================================================
extern "C" void kernel_launch(void* const* d_in, const int* in_sizes, int n_in,
                              void* d_out, int out_size)
{
    const float* x    = (const float*)d_in[0];
    const int*   ei   = (const int*)  d_in[1];
    const float* ew   = (const float*)d_in[2];
    const float* h    = (const float*)d_in[3];
    const float* c    = (const float*)d_in[4];
    const float* Wi   = (const float*)d_in[5];
    const float* bi   = (const float*)d_in[6];
    const float* thi  = (const float*)d_in[7];
    const float* cbi  = (const float*)d_in[8];
    const float* Wf   = (const float*)d_in[9];
    const float* bf   = (const float*)d_in[10];
    const float* thf  = (const float*)d_in[11];
    const float* cbf  = (const float*)d_in[12];
    const float* Wc   = (const float*)d_in[13];
    const float* bc   = (const float*)d_in[14];
    const float* thc  = (const float*)d_in[15];
    const float* cbc  = (const float*)d_in[16];
    const float* Wo   = (const float*)d_in[17];
    const float* bo   = (const float*)d_in[18];
    const float* tho  = (const float*)d_in[19];
    const float* cbo  = (const float*)d_in[20];
    const float* Wlin = (const float*)d_in[21];
    const float* blin = (const float*)d_in[22];
    float* out = (float*)d_out;

    cudaFuncSetAttribute(dense_kernel,
                         cudaFuncAttributeMaxDynamicSharedMemorySize, SM_TOTAL);

    prep_kernel<<<(NN * FOUT / 4 + 255) / 256, 256>>>(Wi, thi, Wf, thf, Wc, thc, Wo, tho);
    deg_kernel<<<(EE + 255) / 256, 256>>>(ei, ew);
    spmm4_kernel<<<(EE * 8 + 255) / 256, 256>>>(ei, ew, h);
    dense_kernel<<<NCTAS, 256, SM_TOTAL>>>(
        x, h, c,
        bi, cbi, bf, cbf, bc, cbc, bo, cbo,
        Wlin, blin, out);
}

// round 12
// speedup vs baseline: 2.3954x; 1.1610x over previous
#include <cuda_runtime.h>
#include <cuda_bf16.h>
#include <cstdint>

#define NN   100000
#define EE   1600000
#define FIN  64
#define FOUT 32
#define NTILE 128
#define NCTAS ((NN + NTILE - 1) / NTILE)   // 782

// -------- scratch (static __device__, no allocations) --------
__device__ __align__(16) float    g_deg[NN];
__device__ __align__(16) float    g_agg[NN * FOUT];
__device__ __align__(16) uint32_t g_Bhi[128 * 64];   // Theta hi, bf16x2 k-pairs, [n][kp]
__device__ __align__(16) uint32_t g_Blo[128 * 64];   // Theta lo

// ===========================================================================
// helpers
// ===========================================================================
__device__ __forceinline__ uint32_t pack_bf2(__nv_bfloat16 a, __nv_bfloat16 b) {
    __nv_bfloat162 t; t.x = a; t.y = b;
    return *(uint32_t*)&t;
}
__device__ __forceinline__ void split2(float a0, float a1, uint32_t& hi, uint32_t& lo) {
    __nv_bfloat16 h0 = __float2bfloat16(a0);
    __nv_bfloat16 h1 = __float2bfloat16(a1);
    float l0 = a0 - __bfloat162float(h0);
    float l1 = a1 - __bfloat162float(h1);
    hi = pack_bf2(h0, h1);
    lo = pack_bf2(__float2bfloat16(l0), __float2bfloat16(l1));
}
__device__ __forceinline__ void hmma(float* d, const uint32_t* a, uint32_t b0, uint32_t b1) {
    asm volatile(
        "mma.sync.aligned.m16n8k16.row.col.f32.bf16.bf16.f32 "
        "{%0,%1,%2,%3}, {%4,%5,%6,%7}, {%8,%9}, {%0,%1,%2,%3};"
        : "+f"(d[0]), "+f"(d[1]), "+f"(d[2]), "+f"(d[3])
        : "r"(a[0]), "r"(a[1]), "r"(a[2]), "r"(a[3]), "r"(b0), "r"(b1));
}
__device__ __forceinline__ float sigf(float v) {
    return __fdividef(1.0f, 1.0f + __expf(-v));
}
__device__ __forceinline__ float tanh_(float v) {
    return fmaf(2.0f, sigf(2.0f * v), -1.0f);
}

// ===========================================================================
// 1) zero deg + agg AND pack combined weights (one launch)
//    Theta[n=g*32+f][k]: k<64: W_g[k][f]; 64..95: th0_g[k-64][f];
//    96..127: -th1_g[k-96][f]  -> hi/lo bf16x2 k-pairs
// ===========================================================================
__global__ void prep_kernel(const float* __restrict__ Wi, const float* __restrict__ thi,
                            const float* __restrict__ Wf, const float* __restrict__ thf,
                            const float* __restrict__ Wc, const float* __restrict__ thc,
                            const float* __restrict__ Wo, const float* __restrict__ tho) {
    int i = blockIdx.x * blockDim.x + threadIdx.x;
    if (i < NN * FOUT / 4)
        ((float4*)g_agg)[i] = make_float4(0.f, 0.f, 0.f, 0.f);
    if (i < NN) g_deg[i] = 0.f;
    if (i < 128 * 64) {
        int n = i >> 6, kp = i & 63;
        int g = n >> 5, f = n & 31;
        const float* W  = (g == 0) ? Wi  : (g == 1) ? Wf  : (g == 2) ? Wc  : Wo;
        const float* th = (g == 0) ? thi : (g == 1) ? thf : (g == 2) ? thc : tho;
        float v[2];
        #pragma unroll
        for (int q = 0; q < 2; q++) {
            int k = kp * 2 + q;
            if (k < 64)      v[q] = W[k * 32 + f];
            else if (k < 96) v[q] = th[(k - 64) * 32 + f];
            else             v[q] = -th[1024 + (k - 96) * 32 + f];
        }
        uint32_t hi, lo;
        split2(v[0], v[1], hi, lo);
        g_Bhi[i] = hi;
        g_Blo[i] = lo;
    }
}

// ===========================================================================
// 2) deg[row] += ew
// ===========================================================================
__global__ void deg_kernel(const int* __restrict__ ei, const float* __restrict__ ew) {
    int e = blockIdx.x * blockDim.x + threadIdx.x;
    if (e < EE) atomicAdd(&g_deg[ei[e]], ew[e]);
}

// ===========================================================================
// 3) scatter SpMM, vector RED + shfl broadcast; rsqrt inline
// ===========================================================================
__device__ __forceinline__ void red4(float* p, float4 v) {
    asm volatile("red.global.add.v4.f32 [%0], {%1, %2, %3, %4};"
                 :: "l"(p), "f"(v.x), "f"(v.y), "f"(v.z), "f"(v.w) : "memory");
}

__global__ void __launch_bounds__(256) spmm4_kernel(const int* __restrict__ ei,
                                                    const float* __restrict__ ew,
                                                    const float* __restrict__ h) {
    int t = blockIdx.x * 256 + threadIdx.x;
    int e = t >> 3;
    if (e >= EE) return;
    int sub  = t & 7;
    int lane = threadIdx.x & 31;
    int src  = lane & ~7;
    int r = 0, c = 0; float w = 0.f;
    if (sub == 0) {
        r = __ldg(ei + e);
        c = __ldg(ei + EE + e);
        float dr = g_deg[r], dc = g_deg[c];
        float ir = (dr > 0.f) ? rsqrtf(dr) : 0.f;
        float ic = (dc > 0.f) ? rsqrtf(dc) : 0.f;
        w = ir * __ldg(ew + e) * ic;
    }
    r = __shfl_sync(0xffffffffu, r, src);
    c = __shfl_sync(0xffffffffu, c, src);
    w = __shfl_sync(0xffffffffu, w, src);
    const float4 hv = *(const float4*)(h + (size_t)c * FOUT + sub * 4);
    red4(g_agg + (size_t)r * FOUT + sub * 4,
         make_float4(w * hv.x, w * hv.y, w * hv.z, w * hv.w));
}

// ===========================================================================
// 4) dense HMMA kernel, A direct-from-global (no A smem), 2 CTAs/SM.
//    B in smem stride 68 (bank = gID*4+tig -> conflict-free fragment loads).
// ===========================================================================
#define ASTRIDE 68      // uint32 words per B row
#define DSTRIDE 129     // float words per D row

#define SM_BHI  0
#define SM_BLO  (SM_BHI + 128 * ASTRIDE * 4)    // 34816
#define SM_BIAS (SM_BLO + 128 * ASTRIDE * 4)    // 69632
#define SM_WL   (SM_BIAS + 128 * 4)             // 70144
#define SM_TOTAL (SM_WL + 32 * 4 + 16)          // ~70.4 KB
// D (float[128][129] = 66048 B) overlays SM_BHI..SM_BIAS (69632 B) after MMA

// load a float2 of A row (node) at element k (compile-time source select)
__device__ __forceinline__ float2 loadA(const float* __restrict__ x,
                                        const float* __restrict__ h,
                                        int node, int k) {
    if (node >= NN) return make_float2(0.f, 0.f);
    if (k < 64)  return __ldg((const float2*)(x + (size_t)node * FIN + k));
    if (k < 96)  return __ldg((const float2*)(h + (size_t)node * FOUT + (k - 64)));
    return *(const float2*)(g_agg + (size_t)node * FOUT + (k - 96));
}

__global__ void __launch_bounds__(256, 2) dense_kernel(
    const float* __restrict__ x, const float* __restrict__ h,
    const float* __restrict__ c,
    const float* __restrict__ bi, const float* __restrict__ cbi,
    const float* __restrict__ bf_, const float* __restrict__ cbf,
    const float* __restrict__ bc, const float* __restrict__ cbc,
    const float* __restrict__ bo, const float* __restrict__ cbo,
    const float* __restrict__ Wlin, const float* __restrict__ blin,
    float* __restrict__ out)
{
    extern __shared__ char sm[];
    uint32_t* sBhi  = (uint32_t*)(sm + SM_BHI);
    uint32_t* sBlo  = (uint32_t*)(sm + SM_BLO);
    float*    sBias = (float*)(sm + SM_BIAS);
    float*    sWl   = (float*)(sm + SM_WL);
    float*    sD    = (float*)(sm + SM_BHI);    // overlay after MMA

    int tid  = threadIdx.x;
    int warp = tid >> 5;
    int lane = tid & 31;
    int gID  = lane >> 2;      // 0..7
    int tig  = lane & 3;       // 0..3

    // ---- load B (pre-packed) into padded smem ----
    for (int i = tid; i < 128 * 64; i += 256) {
        int n = i >> 6, kp = i & 63;
        sBhi[n * ASTRIDE + kp] = g_Bhi[i];
        sBlo[n * ASTRIDE + kp] = g_Blo[i];
    }
    // ---- bias + W_lin ----
    if (tid < 128) {
        int g = tid >> 5, f = tid & 31;
        const float* b  = (g == 0) ? bi  : (g == 1) ? bf_ : (g == 2) ? bc  : bo;
        const float* cb = (g == 0) ? cbi : (g == 1) ? cbf : (g == 2) ? cbc : cbo;
        sBias[tid] = b[f] + cb[f];
        if (tid < 32) sWl[tid] = Wlin[tid];
    }
    __syncthreads();

    // ---- MMA: warp owns 16 node-rows (warp*16 + gID, +8), A from global ----
    float acc[16][4];
    #pragma unroll
    for (int nt = 0; nt < 16; nt++)
        #pragma unroll
        for (int q = 0; q < 4; q++) acc[nt][q] = 0.f;

    int r0 = warp * 16 + gID;          // node-local fragment rows
    int r1 = r0 + 8;
    int n0 = blockIdx.x * NTILE + r0;  // global nodes
    int n1 = blockIdx.x * NTILE + r1;

    #pragma unroll
    for (int ks = 0; ks < 8; ks++) {
        int k0 = ks * 16 + tig * 2;    // element index of first pair
        float2 v00 = loadA(x, h, n0, k0);
        float2 v10 = loadA(x, h, n1, k0);
        float2 v01 = loadA(x, h, n0, k0 + 8);
        float2 v11 = loadA(x, h, n1, k0 + 8);
        uint32_t ah[4], al[4];
        split2(v00.x, v00.y, ah[0], al[0]);
        split2(v10.x, v10.y, ah[1], al[1]);
        split2(v01.x, v01.y, ah[2], al[2]);
        split2(v11.x, v11.y, ah[3], al[3]);

        int kc = ks * 8 + tig;         // bf16x2-pair column in B
        #pragma unroll
        for (int nt = 0; nt < 16; nt++) {
            int nrow = nt * 8 + gID;
            uint32_t bh0 = sBhi[nrow * ASTRIDE + kc];
            uint32_t bh1 = sBhi[nrow * ASTRIDE + kc + 4];
            uint32_t bl0 = sBlo[nrow * ASTRIDE + kc];
            uint32_t bl1 = sBlo[nrow * ASTRIDE + kc + 4];
            hmma(acc[nt], ah, bh0, bh1);
            hmma(acc[nt], al, bh0, bh1);
            hmma(acc[nt], ah, bl0, bl1);
        }
    }
    __syncthreads();   // B dead; safe to overlay D

    // ---- store D to smem ----
    #pragma unroll
    for (int nt = 0; nt < 16; nt++) {
        int col = nt * 8 + tig * 2;
        sD[r0 * DSTRIDE + col]     = acc[nt][0];
        sD[r0 * DSTRIDE + col + 1] = acc[nt][1];
        sD[r1 * DSTRIDE + col]     = acc[nt][2];
        sD[r1 * DSTRIDE + col + 1] = acc[nt][3];
    }
    __syncthreads();

    // ---- epilogue: 2 threads per node ----
    {
        int nl   = tid >> 1;
        int sel  = tid & 1;
        int node = blockIdx.x * NTILE + nl;
        const float* drow = sD + nl * DSTRIDE;
        float part = 0.f;
        if (node < NN) {
            const float* cp = c + (size_t)node * FOUT;
            #pragma unroll
            for (int q = 0; q < 16; q++) {
                int f = sel * 16 + q;
                float vI = sigf (drow[f]      + sBias[f]);
                float vF = sigf (drow[32 + f] + sBias[32 + f]);
                float vT = tanh_(drow[64 + f] + sBias[64 + f]);
                float vO = sigf (drow[96 + f] + sBias[96 + f]);
                float Cn = fmaf(vF, __ldg(cp + f), vI * vT);
                float Hn = vO * tanh_(Cn);
                part = fmaf(fmaxf(Hn, 0.f), sWl[f], part);
            }
        }
        float tot = part + __shfl_xor_sync(0xffffffffu, part, 1);
        if (sel == 0 && node < NN) out[node] = tot + __ldg(blin);
    }
}

// ===========================================================================
extern "C" void kernel_launch(void* const* d_in, const int* in_sizes, int n_in,
                              void* d_out, int out_size)
{
    const float* x    = (const float*)d_in[0];
    const int*   ei   = (const int*)  d_in[1];
    const float* ew   = (const float*)d_in[2];
    const float* h    = (const float*)d_in[3];
    const float* c    = (const float*)d_in[4];
    const float* Wi   = (const float*)d_in[5];
    const float* bi   = (const float*)d_in[6];
    const float* thi  = (const float*)d_in[7];
    const float* cbi  = (const float*)d_in[8];
    const float* Wf   = (const float*)d_in[9];
    const float* bf   = (const float*)d_in[10];
    const float* thf  = (const float*)d_in[11];
    const float* cbf  = (const float*)d_in[12];
    const float* Wc   = (const float*)d_in[13];
    const float* bc   = (const float*)d_in[14];
    const float* thc  = (const float*)d_in[15];
    const float* cbc  = (const float*)d_in[16];
    const float* Wo   = (const float*)d_in[17];
    const float* bo   = (const float*)d_in[18];
    const float* tho  = (const float*)d_in[19];
    const float* cbo  = (const float*)d_in[20];
    const float* Wlin = (const float*)d_in[21];
    const float* blin = (const float*)d_in[22];
    float* out = (float*)d_out;

    cudaFuncSetAttribute(dense_kernel,
                         cudaFuncAttributeMaxDynamicSharedMemorySize, SM_TOTAL);

    prep_kernel<<<(NN * FOUT / 4 + 255) / 256, 256>>>(Wi, thi, Wf, thf, Wc, thc, Wo, tho);
    deg_kernel<<<(EE + 255) / 256, 256>>>(ei, ew);
    spmm4_kernel<<<(EE * 8 + 255) / 256, 256>>>(ei, ew, h);
    dense_kernel<<<NCTAS, 256, SM_TOTAL>>>(
        x, h, c,
        bi, cbi, bf, cbf, bc, cbc, bo, cbo,
        Wlin, blin, out);
}

// round 13
// speedup vs baseline: 2.5279x; 1.0553x over previous
#include <cuda_runtime.h>
#include <cuda_bf16.h>
#include <cstdint>

#define NN   100000
#define EE   1600000
#define FIN  64
#define FOUT 32
#define NTILE 128
#define NCTAS ((NN + NTILE - 1) / NTILE)   // 782

// -------- scratch (static __device__, no allocations) --------
__device__ __align__(16) float    g_deg[NN];
__device__ __align__(16) float    g_agg[NN * FOUT];
__device__ __align__(16) uint32_t g_Bhi[128 * 64];   // Theta hi, bf16x2 k-pairs, [n][kp]
__device__ __align__(16) uint32_t g_Blo[128 * 64];   // Theta lo

// ===========================================================================
// helpers
// ===========================================================================
__device__ __forceinline__ uint32_t pack_bf2(__nv_bfloat16 a, __nv_bfloat16 b) {
    __nv_bfloat162 t; t.x = a; t.y = b;
    return *(uint32_t*)&t;
}
__device__ __forceinline__ void split2(float a0, float a1, uint32_t& hi, uint32_t& lo) {
    __nv_bfloat16 h0 = __float2bfloat16(a0);
    __nv_bfloat16 h1 = __float2bfloat16(a1);
    float l0 = a0 - __bfloat162float(h0);
    float l1 = a1 - __bfloat162float(h1);
    hi = pack_bf2(h0, h1);
    lo = pack_bf2(__float2bfloat16(l0), __float2bfloat16(l1));
}
__device__ __forceinline__ void hmma(float* d, const uint32_t* a, uint32_t b0, uint32_t b1) {
    asm volatile(
        "mma.sync.aligned.m16n8k16.row.col.f32.bf16.bf16.f32 "
        "{%0,%1,%2,%3}, {%4,%5,%6,%7}, {%8,%9}, {%0,%1,%2,%3};"
        : "+f"(d[0]), "+f"(d[1]), "+f"(d[2]), "+f"(d[3])
        : "r"(a[0]), "r"(a[1]), "r"(a[2]), "r"(a[3]), "r"(b0), "r"(b1));
}
__device__ __forceinline__ float sigf(float v) {
    return __fdividef(1.0f, 1.0f + __expf(-v));
}
__device__ __forceinline__ float tanh_(float v) {
    return fmaf(2.0f, sigf(2.0f * v), -1.0f);
}

// ===========================================================================
// 1) zero deg + agg AND pack combined weights (one launch)
//    Theta[n=g*32+f][k]: k<64: W_g[k][f]; 64..95: th0_g[k-64][f];
//    96..127: -th1_g[k-96][f]  -> hi/lo bf16x2 k-pairs
// ===========================================================================
__global__ void prep_kernel(const float* __restrict__ Wi, const float* __restrict__ thi,
                            const float* __restrict__ Wf, const float* __restrict__ thf,
                            const float* __restrict__ Wc, const float* __restrict__ thc,
                            const float* __restrict__ Wo, const float* __restrict__ tho) {
    int i = blockIdx.x * blockDim.x + threadIdx.x;
    if (i < NN * FOUT / 4)
        ((float4*)g_agg)[i] = make_float4(0.f, 0.f, 0.f, 0.f);
    if (i < NN) g_deg[i] = 0.f;
    if (i < 128 * 64) {
        int n = i >> 6, kp = i & 63;
        int g = n >> 5, f = n & 31;
        const float* W  = (g == 0) ? Wi  : (g == 1) ? Wf  : (g == 2) ? Wc  : Wo;
        const float* th = (g == 0) ? thi : (g == 1) ? thf : (g == 2) ? thc : tho;
        float v[2];
        #pragma unroll
        for (int q = 0; q < 2; q++) {
            int k = kp * 2 + q;
            if (k < 64)      v[q] = W[k * 32 + f];
            else if (k < 96) v[q] = th[(k - 64) * 32 + f];
            else             v[q] = -th[1024 + (k - 96) * 32 + f];
        }
        uint32_t hi, lo;
        split2(v[0], v[1], hi, lo);
        g_Bhi[i] = hi;
        g_Blo[i] = lo;
    }
}

// ===========================================================================
// 2) deg[row] += ew
// ===========================================================================
__global__ void deg_kernel(const int* __restrict__ ei, const float* __restrict__ ew) {
    int e = blockIdx.x * blockDim.x + threadIdx.x;
    if (e < EE) atomicAdd(&g_deg[ei[e]], ew[e]);
}

// ===========================================================================
// 3) scatter SpMM, vector RED + shfl broadcast; rsqrt inline
// ===========================================================================
__device__ __forceinline__ void red4(float* p, float4 v) {
    asm volatile("red.global.add.v4.f32 [%0], {%1, %2, %3, %4};"
                 :: "l"(p), "f"(v.x), "f"(v.y), "f"(v.z), "f"(v.w) : "memory");
}

__global__ void __launch_bounds__(256) spmm4_kernel(const int* __restrict__ ei,
                                                    const float* __restrict__ ew,
                                                    const float* __restrict__ h) {
    int t = blockIdx.x * 256 + threadIdx.x;
    int e = t >> 3;
    if (e >= EE) return;
    int sub  = t & 7;
    int lane = threadIdx.x & 31;
    int src  = lane & ~7;
    int r = 0, c = 0; float w = 0.f;
    if (sub == 0) {
        r = __ldg(ei + e);
        c = __ldg(ei + EE + e);
        float dr = g_deg[r], dc = g_deg[c];
        float ir = (dr > 0.f) ? rsqrtf(dr) : 0.f;
        float ic = (dc > 0.f) ? rsqrtf(dc) : 0.f;
        w = ir * __ldg(ew + e) * ic;
    }
    r = __shfl_sync(0xffffffffu, r, src);
    c = __shfl_sync(0xffffffffu, c, src);
    w = __shfl_sync(0xffffffffu, w, src);
    const float4 hv = *(const float4*)(h + (size_t)c * FOUT + sub * 4);
    red4(g_agg + (size_t)r * FOUT + sub * 4,
         make_float4(w * hv.x, w * hv.y, w * hv.z, w * hv.w));
}

// ===========================================================================
// 4) dense HMMA kernel, A direct-from-global, register-resident epilogue.
//    B in smem stride 68 (bank = gID*4+tig -> conflict-free fragment loads).
//    No D staging: for node row r0, its 128 gate columns live in the 4 lanes
//    sharing gID; each lane epilogues its 8 f-values, then shfl_xor(1,2).
// ===========================================================================
#define ASTRIDE 68      // uint32 words per B row

#define SM_BHI  0
#define SM_BLO  (SM_BHI + 128 * ASTRIDE * 4)    // 34816
#define SM_BIAS (SM_BLO + 128 * ASTRIDE * 4)    // 69632
#define SM_WL   (SM_BIAS + 128 * 4)             // 70144
#define SM_TOTAL (SM_WL + 32 * 4 + 16)          // ~70.4 KB -> 3 CTAs/SM

// load a float2 of A row (node) at element k
__device__ __forceinline__ float2 loadA(const float* __restrict__ x,
                                        const float* __restrict__ h,
                                        int node, int k) {
    if (node >= NN) return make_float2(0.f, 0.f);
    if (k < 64)  return __ldg((const float2*)(x + (size_t)node * FIN + k));
    if (k < 96)  return __ldg((const float2*)(h + (size_t)node * FOUT + (k - 64)));
    return *(const float2*)(g_agg + (size_t)node * FOUT + (k - 96));
}

__global__ void __launch_bounds__(256, 3) dense_kernel(
    const float* __restrict__ x, const float* __restrict__ h,
    const float* __restrict__ c,
    const float* __restrict__ bi, const float* __restrict__ cbi,
    const float* __restrict__ bf_, const float* __restrict__ cbf,
    const float* __restrict__ bc, const float* __restrict__ cbc,
    const float* __restrict__ bo, const float* __restrict__ cbo,
    const float* __restrict__ Wlin, const float* __restrict__ blin,
    float* __restrict__ out)
{
    extern __shared__ char sm[];
    uint32_t* sBhi  = (uint32_t*)(sm + SM_BHI);
    uint32_t* sBlo  = (uint32_t*)(sm + SM_BLO);
    float*    sBias = (float*)(sm + SM_BIAS);
    float*    sWl   = (float*)(sm + SM_WL);

    int tid  = threadIdx.x;
    int warp = tid >> 5;
    int lane = tid & 31;
    int gID  = lane >> 2;      // 0..7
    int tig  = lane & 3;       // 0..3

    // ---- load B (pre-packed) into padded smem ----
    for (int i = tid; i < 128 * 64; i += 256) {
        int n = i >> 6, kp = i & 63;
        sBhi[n * ASTRIDE + kp] = g_Bhi[i];
        sBlo[n * ASTRIDE + kp] = g_Blo[i];
    }
    // ---- bias + W_lin ----
    if (tid < 128) {
        int g = tid >> 5, f = tid & 31;
        const float* b  = (g == 0) ? bi  : (g == 1) ? bf_ : (g == 2) ? bc  : bo;
        const float* cb = (g == 0) ? cbi : (g == 1) ? cbf : (g == 2) ? cbc : cbo;
        sBias[tid] = b[f] + cb[f];
        if (tid < 32) sWl[tid] = Wlin[tid];
    }
    __syncthreads();

    // ---- MMA: warp owns 16 node-rows (warp*16 + gID, +8), A from global ----
    float acc[16][4];
    #pragma unroll
    for (int nt = 0; nt < 16; nt++)
        #pragma unroll
        for (int q = 0; q < 4; q++) acc[nt][q] = 0.f;

    int r0 = warp * 16 + gID;          // node-local fragment rows
    int n0 = blockIdx.x * NTILE + r0;  // global nodes
    int n1 = n0 + 8;

    #pragma unroll
    for (int ks = 0; ks < 8; ks++) {
        int k0 = ks * 16 + tig * 2;    // element index of first pair
        float2 v00 = loadA(x, h, n0, k0);
        float2 v10 = loadA(x, h, n1, k0);
        float2 v01 = loadA(x, h, n0, k0 + 8);
        float2 v11 = loadA(x, h, n1, k0 + 8);
        uint32_t ah[4], al[4];
        split2(v00.x, v00.y, ah[0], al[0]);
        split2(v10.x, v10.y, ah[1], al[1]);
        split2(v01.x, v01.y, ah[2], al[2]);
        split2(v11.x, v11.y, ah[3], al[3]);

        int kc = ks * 8 + tig;         // bf16x2-pair column in B
        #pragma unroll
        for (int nt = 0; nt < 16; nt++) {
            int nrow = nt * 8 + gID;
            uint32_t bh0 = sBhi[nrow * ASTRIDE + kc];
            uint32_t bh1 = sBhi[nrow * ASTRIDE + kc + 4];
            uint32_t bl0 = sBlo[nrow * ASTRIDE + kc];
            uint32_t bl1 = sBlo[nrow * ASTRIDE + kc + 4];
            hmma(acc[nt], ah, bh0, bh1);
            hmma(acc[nt], al, bh0, bh1);
            hmma(acc[nt], ah, bl0, bl1);
        }
    }

    // ---- register-resident epilogue ----
    // lane (gID, tig) holds, for rows r0/r1, gate columns {8j + 2tig + q}:
    // I at nt=j, F at nt=4+j, C at nt=8+j, O at nt=12+j.
    float p0 = 0.f, p1 = 0.f;
    #pragma unroll
    for (int j = 0; j < 4; j++) {
        #pragma unroll
        for (int q = 0; q < 2; q++) {
            int f = 8 * j + tig * 2 + q;
            float bI = sBias[f], bF = sBias[32 + f];
            float bT = sBias[64 + f], bO = sBias[96 + f];
            float wl = sWl[f];
            // row r0 (acc[..][q])
            {
                float vI = sigf (acc[j][q]      + bI);
                float vF = sigf (acc[4 + j][q]  + bF);
                float vT = tanh_(acc[8 + j][q]  + bT);
                float vO = sigf (acc[12 + j][q] + bO);
                float cv = (n0 < NN) ? __ldg(c + (size_t)n0 * FOUT + f) : 0.f;
                float Cn = fmaf(vF, cv, vI * vT);
                float Hn = vO * tanh_(Cn);
                p0 = fmaf(fmaxf(Hn, 0.f), wl, p0);
            }
            // row r1 (acc[..][q+2])
            {
                float vI = sigf (acc[j][q + 2]      + bI);
                float vF = sigf (acc[4 + j][q + 2]  + bF);
                float vT = tanh_(acc[8 + j][q + 2]  + bT);
                float vO = sigf (acc[12 + j][q + 2] + bO);
                float cv = (n1 < NN) ? __ldg(c + (size_t)n1 * FOUT + f) : 0.f;
                float Cn = fmaf(vF, cv, vI * vT);
                float Hn = vO * tanh_(Cn);
                p1 = fmaf(fmaxf(Hn, 0.f), wl, p1);
            }
        }
    }
    // reduce over the 4 tig-lanes of this gID group
    p0 += __shfl_xor_sync(0xffffffffu, p0, 1);
    p0 += __shfl_xor_sync(0xffffffffu, p0, 2);
    p1 += __shfl_xor_sync(0xffffffffu, p1, 1);
    p1 += __shfl_xor_sync(0xffffffffu, p1, 2);
    if (tig == 0) {
        float blin0 = __ldg(blin);
        if (n0 < NN) out[n0] = p0 + blin0;
        if (n1 < NN) out[n1] = p1 + blin0;
    }
}

// ===========================================================================
extern "C" void kernel_launch(void* const* d_in, const int* in_sizes, int n_in,
                              void* d_out, int out_size)
{
    const float* x    = (const float*)d_in[0];
    const int*   ei   = (const int*)  d_in[1];
    const float* ew   = (const float*)d_in[2];
    const float* h    = (const float*)d_in[3];
    const float* c    = (const float*)d_in[4];
    const float* Wi   = (const float*)d_in[5];
    const float* bi   = (const float*)d_in[6];
    const float* thi  = (const float*)d_in[7];
    const float* cbi  = (const float*)d_in[8];
    const float* Wf   = (const float*)d_in[9];
    const float* bf   = (const float*)d_in[10];
    const float* thf  = (const float*)d_in[11];
    const float* cbf  = (const float*)d_in[12];
    const float* Wc   = (const float*)d_in[13];
    const float* bc   = (const float*)d_in[14];
    const float* thc  = (const float*)d_in[15];
    const float* cbc  = (const float*)d_in[16];
    const float* Wo   = (const float*)d_in[17];
    const float* bo   = (const float*)d_in[18];
    const float* tho  = (const float*)d_in[19];
    const float* cbo  = (const float*)d_in[20];
    const float* Wlin = (const float*)d_in[21];
    const float* blin = (const float*)d_in[22];
    float* out = (float*)d_out;

    cudaFuncSetAttribute(dense_kernel,
                         cudaFuncAttributeMaxDynamicSharedMemorySize, SM_TOTAL);

    prep_kernel<<<(NN * FOUT / 4 + 255) / 256, 256>>>(Wi, thi, Wf, thf, Wc, thc, Wo, tho);
    deg_kernel<<<(EE + 255) / 256, 256>>>(ei, ew);
    spmm4_kernel<<<(EE * 8 + 255) / 256, 256>>>(ei, ew, h);
    dense_kernel<<<NCTAS, 256, SM_TOTAL>>>(
        x, h, c,
        bi, cbi, bf, cbf, bc, cbc, bo, cbo,
        Wlin, blin, out);
}